// round 1
// baseline (speedup 1.0000x reference)
#include <cuda_runtime.h>
#include <math.h>

// ---------------- problem constants ----------------
#define BB 2
#define FMC 1024
#define HID 512
#define HW 32            // feature map H = W = 32
#define POS 1024         // 32*32
#define NA 9
#define NANCH 9216       // POS*NA
#define NC 21
#define TOPK 20
#define POOL 7
#define NEGV -1e30f

// out layout (floats): rpn_reg | rpn_cls | nms_reg | nms_cls | rcnn_reg | rcnn_cls | anchors
#define OFF_RPN_REG 0
#define OFF_RPN_CLS 73728
#define OFF_NMS_REG 92160
#define OFF_NMS_CLS 92320
#define OFF_RCNN_REG 92360
#define OFF_RCNN_CLS 92520
#define OFF_ANCH 93360

// ---------------- scratch ----------------
__device__ float g_fm[BB * FMC * POS];        // 8 MB
__device__ float g_h[BB * HID * POS];         // 4 MB
__device__ float g_boxes[BB * NANCH * 4];     // reg + anchors (NMS input)
__device__ float g_pooled[BB * TOPK * FMC * POOL * POOL]; // 40 x 50176
__device__ float g_hf[BB * TOPK * 1024];

// ---------------- tiled GEMM conv kernels ----------------
#define BM 64
#define BN 64
#define BK 16
#define BNP 68   // pad so float4 rows stay 16B-aligned, conflicts ~2-way

// conv1: patch-embed GEMM. M=2048 (b,y,x), N=1024, K=768 (ic*256+kh*16+kw)
__global__ void k_conv1(const float* __restrict__ img, const float* __restrict__ w,
                        const float* __restrict__ bias, float* __restrict__ fm) {
    __shared__ float As[BK][BM];
    __shared__ float Bs[BK][BNP];
    int bm = blockIdx.x * BM, bn = blockIdx.y * BN;
    int tid = threadIdx.x;
    int tx = tid & 15, ty = tid >> 4;
    float acc[4][4] = {};
    for (int k0 = 0; k0 < 768; k0 += BK) {
#pragma unroll
        for (int s = 0; s < 4; s++) {
            int i = tid + s * 256;
            int mm = i & (BM - 1), kk = i >> 6;
            int m = bm + mm, k = k0 + kk;
            int b = m >> 10, rem = m & 1023;
            int y = rem >> 5, x = rem & 31;
            int ic = k >> 8, r = k & 255, kh = r >> 4, kw = r & 15;
            As[kk][mm] = img[((b * 3 + ic) * 512 + (y * 16 + kh)) * 512 + (x * 16 + kw)];
        }
#pragma unroll
        for (int s = 0; s < 4; s++) {
            int i = tid + s * 256;
            int kk = i & (BK - 1), nn = i >> 4;
            Bs[kk][nn] = w[(size_t)(bn + nn) * 768 + (k0 + kk)];
        }
        __syncthreads();
#pragma unroll
        for (int kk = 0; kk < BK; kk++) {
            float4 a4 = *(const float4*)&As[kk][ty * 4];
            float4 b4 = *(const float4*)&Bs[kk][tx * 4];
            float a[4] = {a4.x, a4.y, a4.z, a4.w};
            float bv[4] = {b4.x, b4.y, b4.z, b4.w};
#pragma unroll
            for (int i2 = 0; i2 < 4; i2++)
#pragma unroll
                for (int j = 0; j < 4; j++)
                    acc[i2][j] = fmaf(a[i2], bv[j], acc[i2][j]);
        }
        __syncthreads();
    }
#pragma unroll
    for (int i2 = 0; i2 < 4; i2++) {
        int m = bm + ty * 4 + i2;
        int b = m >> 10, rem = m & 1023;
#pragma unroll
        for (int j = 0; j < 4; j++) {
            int n = bn + tx * 4 + j;
            fm[((size_t)b * FMC + n) * POS + rem] = fmaxf(acc[i2][j] + bias[n], 0.f);
        }
    }
}

// conv2 (rpn 3x3 SAME): implicit GEMM. M=2048, N=512, K=9216 (ic*9+kh*3+kw)
__global__ void k_conv2(const float* __restrict__ fm, const float* __restrict__ w,
                        const float* __restrict__ bias, float* __restrict__ h) {
    __shared__ float As[BK][BM];
    __shared__ float Bs[BK][BNP];
    int bm = blockIdx.x * BM, bn = blockIdx.y * BN;
    int tid = threadIdx.x;
    int tx = tid & 15, ty = tid >> 4;
    float acc[4][4] = {};
    for (int k0 = 0; k0 < 9216; k0 += BK) {
#pragma unroll
        for (int s = 0; s < 4; s++) {
            int i = tid + s * 256;
            int mm = i & (BM - 1), kk = i >> 6;
            int m = bm + mm, k = k0 + kk;
            int b = m >> 10, rem = m & 1023;
            int y = rem >> 5, x = rem & 31;
            int ic = k / 9, r = k - ic * 9;
            int kh = r / 3, kw = r - kh * 3;
            int iy = y + kh - 1, ix = x + kw - 1;
            float v = 0.f;
            if (iy >= 0 && iy < HW && ix >= 0 && ix < HW)
                v = fm[((size_t)b * FMC + ic) * POS + iy * HW + ix];
            As[kk][mm] = v;
        }
#pragma unroll
        for (int s = 0; s < 4; s++) {
            int i = tid + s * 256;
            int kk = i & (BK - 1), nn = i >> 4;
            Bs[kk][nn] = w[(size_t)(bn + nn) * 9216 + (k0 + kk)];
        }
        __syncthreads();
#pragma unroll
        for (int kk = 0; kk < BK; kk++) {
            float4 a4 = *(const float4*)&As[kk][ty * 4];
            float4 b4 = *(const float4*)&Bs[kk][tx * 4];
            float a[4] = {a4.x, a4.y, a4.z, a4.w};
            float bv[4] = {b4.x, b4.y, b4.z, b4.w};
#pragma unroll
            for (int i2 = 0; i2 < 4; i2++)
#pragma unroll
                for (int j = 0; j < 4; j++)
                    acc[i2][j] = fmaf(a[i2], bv[j], acc[i2][j]);
        }
        __syncthreads();
    }
#pragma unroll
    for (int i2 = 0; i2 < 4; i2++) {
        int m = bm + ty * 4 + i2;
        int b = m >> 10, rem = m & 1023;
#pragma unroll
        for (int j = 0; j < 4; j++) {
            int n = bn + tx * 4 + j;
            h[((size_t)b * HID + n) * POS + rem] = fmaxf(acc[i2][j] + bias[n], 0.f);
        }
    }
}

// ---------------- rpn heads (1x1 convs) + anchors + boxes ----------------
__global__ void k_heads(const float* __restrict__ h,
                        const float* __restrict__ regw, const float* __restrict__ regb,
                        const float* __restrict__ clsw, const float* __restrict__ clsb,
                        float* __restrict__ o_reg, float* __restrict__ o_cls,
                        float* __restrict__ o_anch, float* __restrict__ boxes) {
    int flat = blockIdx.x * 256 + threadIdx.x;   // < 2*1024*45 = 92160
    int b = flat / 46080;
    int rem = flat - b * 46080;
    int pos = rem / 45, o = rem - pos * 45;
    int y = pos >> 5, x = pos & 31;
    const float* hb = h + (size_t)b * HID * POS + pos;
    if (o < 36) {
        const float* wr = regw + o * HID;
        float acc = regb[o];
        for (int c = 0; c < HID; c++) acc = fmaf(hb[(size_t)c * POS], wr[c], acc);
        int a = o >> 2, j = o & 3;
        int si = a / 3, ri = a - si * 3;
        double s = 64.0 * (double)(1 << si);
        double rr = (ri == 0) ? 0.5 : (ri == 1 ? 1.0 : 2.0);
        float aw = (float)(s * sqrt(rr));
        float ah = (float)(s / sqrt(rr));
        float cx = (x + 0.5f) * 16.f, cy = (y + 0.5f) * 16.f;
        float anc;
        if (j == 0) anc = cx - aw * 0.5f;
        else if (j == 1) anc = cy - ah * 0.5f;
        else if (j == 2) anc = cx + aw * 0.5f;
        else anc = cy + ah * 0.5f;
        int oi = (pos * NA + a) * 4 + j;
        o_reg[b * (NANCH * 4) + oi] = acc;
        boxes[b * (NANCH * 4) + oi] = acc + anc;
        if (b == 0) o_anch[oi] = anc;
    } else {
        int a = o - 36;
        const float* wc = clsw + a * HID;
        float acc = clsb[a];
        for (int c = 0; c < HID; c++) acc = fmaf(hb[(size_t)c * POS], wc[c], acc);
        o_cls[b * NANCH + pos * NA + a] = acc;
    }
}

// ---------------- NMS (one block per batch) ----------------
__global__ void k_nms(const float* __restrict__ boxes, const float* __restrict__ scores,
                      float* __restrict__ o_nreg, float* __restrict__ o_ncls) {
    int b = blockIdx.x;
    int tid = threadIdx.x;  // 1024
    __shared__ float sc[NANCH];
    __shared__ float rv[1024];
    __shared__ int   ri[1024];
    __shared__ float selb[4];
    __shared__ int   seli;
    float bx1[9], by1[9], bx2[9], by2[9], barea[9];
#pragma unroll
    for (int t = 0; t < 9; t++) {
        int idx = tid + t * 1024;
        const float* bp = boxes + ((size_t)b * NANCH + idx) * 4;
        bx1[t] = bp[0]; by1[t] = bp[1]; bx2[t] = bp[2]; by2[t] = bp[3];
        barea[t] = fmaxf(bx2[t] - bx1[t], 0.f) * fmaxf(by2[t] - by1[t], 0.f);
        sc[idx] = scores[b * NANCH + idx];
    }
    __syncthreads();
    for (int it = 0; it < TOPK; it++) {
        float best = -INFINITY; int bi = 0x7fffffff;
#pragma unroll
        for (int t = 0; t < 9; t++) {
            int idx = tid + t * 1024;
            float v = sc[idx];
            if (v > best) { best = v; bi = idx; }   // strict > => first (lowest) idx on tie
        }
        rv[tid] = best; ri[tid] = bi;
        __syncthreads();
        for (int s = 512; s > 0; s >>= 1) {
            if (tid < s) {
                float v2 = rv[tid + s]; int i2 = ri[tid + s];
                if (v2 > rv[tid] || (v2 == rv[tid] && i2 < ri[tid])) { rv[tid] = v2; ri[tid] = i2; }
            }
            __syncthreads();
        }
        if (tid == 0) {
            int i = ri[0];
            seli = i;
            const float* bp = boxes + ((size_t)b * NANCH + i) * 4;
            selb[0] = bp[0]; selb[1] = bp[1]; selb[2] = bp[2]; selb[3] = bp[3];
            o_ncls[b * TOPK + it] = rv[0];
            float* oo = o_nreg + (b * TOPK + it) * 4;
            oo[0] = bp[0]; oo[1] = bp[1]; oo[2] = bp[2]; oo[3] = bp[3];
        }
        __syncthreads();
        float s1 = selb[0], s2 = selb[1], s3 = selb[2], s4 = selb[3];
        float sarea = fmaxf(s3 - s1, 0.f) * fmaxf(s4 - s2, 0.f);
        int si_ = seli;
#pragma unroll
        for (int t = 0; t < 9; t++) {
            int idx = tid + t * 1024;
            float ix1 = fmaxf(s1, bx1[t]);
            float iy1 = fmaxf(s2, by1[t]);
            float ix2 = fminf(s3, bx2[t]);
            float iy2 = fminf(s4, by2[t]);
            float inter = fmaxf(ix2 - ix1, 0.f) * fmaxf(iy2 - iy1, 0.f);
            float iou = inter / (sarea + barea[t] - inter + 1e-8f);
            if (iou > 0.3f || idx == si_) sc[idx] = NEGV;
        }
        __syncthreads();
    }
}

// ---------------- ROI align ----------------
__global__ void k_roi(const float* __restrict__ fm, const int* __restrict__ img_id,
                      const float* __restrict__ nreg, float* __restrict__ pooled) {
    int br = blockIdx.x;                 // 0..39  (b*20 + r)
    int b = br / TOPK;
    int cchunk = blockIdx.y;             // 0..7 -> 128 channels
    __shared__ int sx0[POOL], sx1[POOL], sy0[POOL], sy1[POOL];
    __shared__ float slx[POOL], sly[POOL];
    int tid = threadIdx.x;
    if (tid < POOL) {
        const float* bx = nreg + br * 4;
        float b0 = bx[0] / 16.f, b1 = bx[1] / 16.f, b2 = bx[2] / 16.f, b3 = bx[3] / 16.f;
        float t = ((float)tid + 0.5f) / (float)POOL;
        float xs = b0 + fmaxf(b2 - b0, 0.f) * t;
        float x = fminf(fmaxf(xs, 0.f), 31.f);
        float x0f = floorf(x);
        sx0[tid] = (int)x0f; sx1[tid] = min((int)x0f + 1, 31); slx[tid] = x - x0f;
        float ys = b1 + fmaxf(b3 - b1, 0.f) * t;
        float yv = fminf(fmaxf(ys, 0.f), 31.f);
        float y0f = floorf(yv);
        sy0[tid] = (int)y0f; sy1[tid] = min((int)y0f + 1, 31); sly[tid] = yv - y0f;
    }
    __syncthreads();
    const float* fmb = fm + (size_t)img_id[b] * FMC * POS;
    for (int i = tid; i < 128 * POOL * POOL; i += blockDim.x) {
        int c = cchunk * 128 + i / 49;
        int p = i % 49;
        int py = p / 7, px = p - py * 7;
        const float* base = fmb + (size_t)c * POS;
        float lx = slx[px], ly = sly[py];
        float v00 = base[sy0[py] * HW + sx0[px]];
        float v01 = base[sy0[py] * HW + sx1[px]];
        float v10 = base[sy1[py] * HW + sx0[px]];
        float v11 = base[sy1[py] * HW + sx1[px]];
        float outv = v00 * (1.f - ly) * (1.f - lx) + v01 * (1.f - ly) * lx
                   + v10 * ly * (1.f - lx) + v11 * ly * lx;
        pooled[((size_t)br * FMC + c) * 49 + p] = outv;
    }
}

// ---------------- FC: 40 x 50176 @ 50176 x 1024 ----------------
__global__ void k_zero(float* __restrict__ p, int n) {
    int i = blockIdx.x * blockDim.x + threadIdx.x;
    if (i < n) p[i] = 0.f;
}

// blockDim 320 = 64 n-quads x 5 m-groups(8 rows each); grid (4 nblocks, 98 kchunks)
__global__ void k_fc(const float* __restrict__ A, const float* __restrict__ W,
                     float* __restrict__ accum) {
    int tid = threadIdx.x;
    int tn = tid & 63, tm = tid >> 6;   // tm 0..4
    int n = (blockIdx.x * 64 + tn) * 4;
    int m0 = tm * 8;
    int k0 = blockIdx.y * 512;
    float acc[8][4] = {};
#pragma unroll 2
    for (int k = k0; k < k0 + 512; k++) {
        float4 w4 = *(const float4*)&W[(size_t)k * 1024 + n];
#pragma unroll
        for (int m = 0; m < 8; m++) {
            float a = A[(size_t)(m0 + m) * 50176 + k];
            acc[m][0] = fmaf(a, w4.x, acc[m][0]);
            acc[m][1] = fmaf(a, w4.y, acc[m][1]);
            acc[m][2] = fmaf(a, w4.z, acc[m][2]);
            acc[m][3] = fmaf(a, w4.w, acc[m][3]);
        }
    }
#pragma unroll
    for (int m = 0; m < 8; m++)
#pragma unroll
        for (int j = 0; j < 4; j++)
            atomicAdd(&accum[(m0 + m) * 1024 + n + j], acc[m][j]);
}

__global__ void k_fc_fin(float* __restrict__ hf, const float* __restrict__ fcb) {
    int i = blockIdx.x * blockDim.x + threadIdx.x;
    if (i < 40 * 1024) {
        int nn = i & 1023;
        hf[i] = fmaxf(hf[i] + fcb[nn], 0.f);
    }
}

// ---------------- final heads ----------------
__global__ void k_head2(const float* __restrict__ hf,
                        const float* __restrict__ regw, const float* __restrict__ regb,
                        const float* __restrict__ clsw, const float* __restrict__ clsb,
                        float* __restrict__ o_rreg, float* __restrict__ o_rcls) {
    int t = blockIdx.x * blockDim.x + threadIdx.x;
    if (t >= 40 * 25) return;
    int m = t / 25, j = t - m * 25;
    const float* hr = hf + m * 1024;
    if (j < 4) {
        float acc = regb[j];
        for (int k = 0; k < 1024; k++) acc = fmaf(hr[k], regw[k * 4 + j], acc);
        o_rreg[m * 4 + j] = acc;
    } else {
        int jj = j - 4;
        float acc = clsb[jj];
        for (int k = 0; k < 1024; k++) acc = fmaf(hr[k], clsw[k * 21 + jj], acc);
        o_rcls[m * 21 + jj] = acc;
    }
}

// ---------------- launch ----------------
extern "C" void kernel_launch(void* const* d_in, const int* in_sizes, int n_in,
                              void* d_out, int out_size) {
    const float* img       = (const float*)d_in[0];
    const int*   img_id    = (const int*)d_in[1];
    const float* cnn_w     = (const float*)d_in[2];
    const float* cnn_b     = (const float*)d_in[3];
    const float* rpn_w     = (const float*)d_in[4];
    const float* rpn_b     = (const float*)d_in[5];
    const float* rpn_reg_w = (const float*)d_in[6];
    const float* rpn_reg_b = (const float*)d_in[7];
    const float* rpn_cls_w = (const float*)d_in[8];
    const float* rpn_cls_b = (const float*)d_in[9];
    const float* fc_w      = (const float*)d_in[10];
    const float* fc_b      = (const float*)d_in[11];
    const float* reg_w     = (const float*)d_in[12];
    const float* reg_b     = (const float*)d_in[13];
    const float* cls_w     = (const float*)d_in[14];
    const float* cls_b     = (const float*)d_in[15];
    float* out = (float*)d_out;

    float* g_fm_p;     cudaGetSymbolAddress((void**)&g_fm_p, g_fm);
    float* g_h_p;      cudaGetSymbolAddress((void**)&g_h_p, g_h);
    float* g_boxes_p;  cudaGetSymbolAddress((void**)&g_boxes_p, g_boxes);
    float* g_pooled_p; cudaGetSymbolAddress((void**)&g_pooled_p, g_pooled);
    float* g_hf_p;     cudaGetSymbolAddress((void**)&g_hf_p, g_hf);

    // 1. patch-embed conv (stride=kernel=16, VALID) + relu
    k_conv1<<<dim3(32, 16), 256>>>(img, cnn_w, cnn_b, g_fm_p);
    // 2. rpn 3x3 SAME conv + relu
    k_conv2<<<dim3(32, 8), 256>>>(g_fm_p, rpn_w, rpn_b, g_h_p);
    // 3. 1x1 heads + anchors + proposal boxes
    k_heads<<<360, 256>>>(g_h_p, rpn_reg_w, rpn_reg_b, rpn_cls_w, rpn_cls_b,
                          out + OFF_RPN_REG, out + OFF_RPN_CLS, out + OFF_ANCH, g_boxes_p);
    // 4. NMS (TOP=20, IoU 0.3)
    k_nms<<<BB, 1024>>>(g_boxes_p, out + OFF_RPN_CLS, out + OFF_NMS_REG, out + OFF_NMS_CLS);
    // 5. ROI align 7x7 over 1024 channels
    k_roi<<<dim3(BB * TOPK, 8), 256>>>(g_fm_p, img_id, out + OFF_NMS_REG, g_pooled_p);
    // 6. FC 40x50176x1024 + bias + relu
    k_zero<<<(40 * 1024 + 255) / 256, 256>>>(g_hf_p, 40 * 1024);
    k_fc<<<dim3(4, 98), 320>>>(g_pooled_p, fc_w, g_hf_p);
    k_fc_fin<<<(40 * 1024 + 255) / 256, 256>>>(g_hf_p, fc_b);
    // 7. rcnn reg/cls heads
    k_head2<<<4, 256>>>(g_hf_p, reg_w, reg_b, cls_w, cls_b,
                        out + OFF_RCNN_REG, out + OFF_RCNN_CLS);
}